// round 6
// baseline (speedup 1.0000x reference)
#include <cuda_runtime.h>
#include <cuda_bf16.h>

// Problem constants
#define BB   64
#define LL   512
#define HH   256
#define HD   128
#define NG   512            // 4 * HD gates
#define M_TOT (BB*LL)       // 32768 cells / rows

// 64 MB scratch for precomputed input gates: g_pre[m][n] = feats[m]@W_ih^T + b_ih + b_hh
__device__ float g_pre[(size_t)M_TOT * NG];

__device__ __forceinline__ unsigned f2tf(float x) {
    unsigned r;
    asm("cvt.rna.tf32.f32 %0, %1;" : "=r"(r) : "f"(x));
    return r;
}

__device__ __forceinline__ void mma_tf32(float c[4],
                                         unsigned a0, unsigned a1, unsigned a2, unsigned a3,
                                         unsigned b0, unsigned b1) {
    asm volatile(
        "mma.sync.aligned.m16n8k8.row.col.f32.tf32.tf32.f32 "
        "{%0,%1,%2,%3}, {%4,%5,%6,%7}, {%8,%9}, {%0,%1,%2,%3};"
        : "+f"(c[0]), "+f"(c[1]), "+f"(c[2]), "+f"(c[3])
        : "r"(a0), "r"(a1), "r"(a2), "r"(a3), "r"(b0), "r"(b1));
}

__device__ __forceinline__ void cp_async16(void* smem_dst, const void* gptr) {
    unsigned s = (unsigned)__cvta_generic_to_shared(smem_dst);
    asm volatile("cp.async.cg.shared.global [%0], [%1], 16;" :: "r"(s), "l"(gptr));
}
__device__ __forceinline__ void cp_async_commit_wait() {
    asm volatile("cp.async.commit_group;");
    asm volatile("cp.async.wait_group 0;");
}

__device__ __forceinline__ float sigm(float x)  { return 1.f / (1.f + __expf(-x)); }
__device__ __forceinline__ float tanhx(float x) { return 2.f / (1.f + __expf(-2.f * x)) - 1.f; }

// ---------------------------------------------------------------------------
// Kernel A: g_pre = tf32_mma(feats @ W_ih^T) + (b_ih + b_hh)
// Block tile 128(M) x 256(N), K=256 in chunks of 32. 8 warps = 2(M) x 4(N).
// ---------------------------------------------------------------------------
#define BMA 128
#define BNA 256
#define BKA 32
#define ASTR 36

__global__ __launch_bounds__(256, 1) void pre_gemm_kernel(
    const float* __restrict__ A,     // feats  [M_TOT][HH]
    const float* __restrict__ W,     // W_ih   [NG][HH]
    const float* __restrict__ b_ih,
    const float* __restrict__ b_hh,
    const int*   __restrict__ lens)
{
    const int m0 = blockIdx.x * BMA;
    const int n0 = blockIdx.y * BNA;
    const int b  = m0 / LL;
    const int j0 = m0 % LL;
    if (j0 >= lens[b] + 3) return;   // rows never consumed

    extern __shared__ __align__(16) unsigned smA[];
    unsigned* As = smA;                  // [128][ASTR]
    unsigned* Bs = smA + BMA * ASTR;     // [256][ASTR]

    const int t    = threadIdx.x;
    const int wid  = t >> 5;
    const int lane = t & 31;
    const int g    = lane >> 2;
    const int tq   = lane & 3;
    const int mw   = (wid & 1) * 64;
    const int nw   = (wid >> 1) * 64;

    float acc[4][8][4];
#pragma unroll
    for (int mi = 0; mi < 4; mi++)
#pragma unroll
        for (int ni = 0; ni < 8; ni++)
#pragma unroll
            for (int r = 0; r < 4; r++) acc[mi][ni][r] = 0.f;

#pragma unroll 1
    for (int kc = 0; kc < HH; kc += BKA) {
        __syncthreads();
#pragma unroll
        for (int it = 0; it < 4; it++) {
            int idx = t + 256 * it;          // 0..1023
            int row = idx >> 3;
            int k4  = (idx & 7) * 4;
            float4 v = *(const float4*)(A + (size_t)(m0 + row) * HH + kc + k4);
            uint4 u = make_uint4(f2tf(v.x), f2tf(v.y), f2tf(v.z), f2tf(v.w));
            *(uint4*)(As + row * ASTR + k4) = u;
        }
#pragma unroll
        for (int it = 0; it < 8; it++) {
            int idx = t + 256 * it;          // 0..2047
            int row = idx >> 3;
            int k4  = (idx & 7) * 4;
            float4 v = *(const float4*)(W + (size_t)(n0 + row) * HH + kc + k4);
            uint4 u = make_uint4(f2tf(v.x), f2tf(v.y), f2tf(v.z), f2tf(v.w));
            *(uint4*)(Bs + row * ASTR + k4) = u;
        }
        __syncthreads();

#pragma unroll
        for (int ks = 0; ks < BKA / 8; ks++) {
            const int kk = ks * 8;
            unsigned a[4][4];
#pragma unroll
            for (int mi = 0; mi < 4; mi++) {
                const unsigned* p = As + (mw + mi * 16 + g) * ASTR + kk + tq;
                a[mi][0] = p[0];
                a[mi][1] = p[8 * ASTR];
                a[mi][2] = p[4];
                a[mi][3] = p[8 * ASTR + 4];
            }
#pragma unroll
            for (int ni = 0; ni < 8; ni++) {
                const unsigned* p = Bs + (nw + ni * 8 + g) * ASTR + kk + tq;
                unsigned b0 = p[0], b1 = p[4];
#pragma unroll
                for (int mi = 0; mi < 4; mi++)
                    mma_tf32(acc[mi][ni], a[mi][0], a[mi][1], a[mi][2], a[mi][3], b0, b1);
            }
        }
    }

#pragma unroll
    for (int ni = 0; ni < 8; ni++) {
        const int n = n0 + nw + ni * 8 + 2 * tq;
        const float bv0 = b_ih[n] + b_hh[n];
        const float bv1 = b_ih[n + 1] + b_hh[n + 1];
#pragma unroll
        for (int mi = 0; mi < 4; mi++) {
            const int m = m0 + mw + mi * 16 + g;
            float2 v01 = make_float2(acc[mi][ni][0] + bv0, acc[mi][ni][1] + bv1);
            float2 v23 = make_float2(acc[mi][ni][2] + bv0, acc[mi][ni][3] + bv1);
            *(float2*)(g_pre + (size_t)m * NG + n)       = v01;
            *(float2*)(g_pre + (size_t)(m + 8) * NG + n) = v23;
        }
    }
}

// ---------------------------------------------------------------------------
// Kernel B: fused 4-step LSTM recurrence (tf32 mma) + emit + scatter.
// Block = 64 cells, 512 threads / 16 warps = 2 M-rows (32 cells) x 8 hd-windows.
// Warp (mrow, w) owns cells [mrow*32, mrow*32+32) x hd [w*16, w*16+16) across
// ALL 4 gates -> pointwise LSTM is register-local. c in regs; h via smem.
// W_hh chunk staged raw fp32 via cp.async; cvt to tf32 at fragment load.
// ---------------------------------------------------------------------------
#define KCB 32
#define HSTR (HD + 4)   // 132: A-frag loads hit banks 4g+tq, conflict-free
#define WSTR (KCB + 4)  // 36:  B-frag loads hit banks 4g+tq, conflict-free

__global__ __launch_bounds__(512, 1) void lstm_mma_kernel(
    const float* __restrict__ Whh,   // [NG][HD]
    const float* __restrict__ b_ih,
    const float* __restrict__ b_hh,
    const float* __restrict__ Wtri,  // [2][HD]
    const float* __restrict__ btri,  // [2]
    const int*   __restrict__ lens,
    float*       __restrict__ out)   // [BB][LL][LL][2]
{
    const int blk = blockIdx.x;
    const int b   = blk >> 3;
    const int i0  = (blk & 7) * 64;
    const int len = lens[b];
    if (i0 >= len) return;

    extern __shared__ __align__(16) float sm[];
    float* Hs    = sm;                       // [64][HSTR] fp32 h
    float* Wsf   = sm + 64 * HSTR;           // [NG][WSTR] fp32 W chunk
    float* biasS = Wsf + NG * WSTR;          // [NG]
    float* WtS   = biasS + NG;               // [256]

    const int t    = threadIdx.x;
    const int wid  = t >> 5;
    const int lane = t & 31;
    const int g    = lane >> 2;
    const int tq   = lane & 3;
    const int w    = wid & 7;                // hd window
    const int mrow = wid >> 3;               // 0/1: cells mrow*32 ..

    if (t < 256) WtS[t] = Wtri[t];
    if (t < NG)  biasS[t] = b_ih[t] + b_hh[t];
    __syncthreads();

    float cst[2][2][4];
#pragma unroll
    for (int mi = 0; mi < 2; mi++)
#pragma unroll
        for (int s = 0; s < 2; s++)
#pragma unroll
            for (int r = 0; r < 4; r++) cst[mi][s][r] = 0.f;

    int nsteps = len - i0;
    if (nsteps > 4) nsteps = 4;
    const size_t rowBase = (size_t)b * LL;

#pragma unroll 1
    for (int st = 1; st <= 4; st++) {
        // ---- 1) acc init from g_pre (bias for padded rows)
        float acc[2][4][2][4];   // [mi][gate][s][r]
#pragma unroll
        for (int mi = 0; mi < 2; mi++) {
            const int cell0 = mrow * 32 + mi * 16 + g;
            const int jA = i0 + cell0 + st - 1;       // rows for r0/r1
            const int jB = jA + 8;                    // rows for r2/r3
            const float* srcA = (jA < LL) ? (g_pre + (rowBase + jA) * NG) : biasS;
            const float* srcB = (jB < LL) ? (g_pre + (rowBase + jB) * NG) : biasS;
#pragma unroll
            for (int gi = 0; gi < 4; gi++)
#pragma unroll
                for (int s = 0; s < 2; s++) {
                    const int n = gi * 128 + w * 16 + s * 8 + 2 * tq;
                    float2 vA = *(const float2*)(srcA + n);
                    float2 vB = *(const float2*)(srcB + n);
                    acc[mi][gi][s][0] = vA.x; acc[mi][gi][s][1] = vA.y;
                    acc[mi][gi][s][2] = vB.x; acc[mi][gi][s][3] = vB.y;
                }
        }

        // ---- 2) recurrent tf32 mma: acc += H_prev @ W_hh^T  (h0 = 0 -> skip st 1)
        if (st > 1) {
#pragma unroll 1
            for (int kc = 0; kc < HD; kc += KCB) {
                __syncthreads();   // previous chunk readers done
                // stage W chunk [NG][KCB] raw fp32 via cp.async (16B per copy)
#pragma unroll
                for (int it = 0; it < 8; it++) {
                    int idx = t + 512 * it;       // 0..4095
                    int n   = idx >> 3;           // 0..511
                    int k4  = (idx & 7) * 4;      // 0..28
                    cp_async16(Wsf + n * WSTR + k4, Whh + (size_t)n * HD + kc + k4);
                }
                cp_async_commit_wait();
                __syncthreads();
#pragma unroll
                for (int ks = 0; ks < KCB / 8; ks++) {
                    const int kk = ks * 8;
                    unsigned a[2][4];
#pragma unroll
                    for (int mi = 0; mi < 2; mi++) {
                        const float* p = Hs + (mrow * 32 + mi * 16 + g) * HSTR + kc + kk + tq;
                        a[mi][0] = f2tf(p[0]);
                        a[mi][1] = f2tf(p[8 * HSTR]);
                        a[mi][2] = f2tf(p[4]);
                        a[mi][3] = f2tf(p[8 * HSTR + 4]);
                    }
#pragma unroll
                    for (int gi = 0; gi < 4; gi++)
#pragma unroll
                        for (int s = 0; s < 2; s++) {
                            const int n = gi * 128 + w * 16 + s * 8 + g;
                            const float* p = Wsf + n * WSTR + kk + tq;
                            unsigned b0 = f2tf(p[0]), b1 = f2tf(p[4]);
#pragma unroll
                            for (int mi = 0; mi < 2; mi++)
                                mma_tf32(acc[mi][gi][s],
                                         a[mi][0], a[mi][1], a[mi][2], a[mi][3], b0, b1);
                        }
                }
            }
            __syncthreads();   // all warps done reading Hs before overwrite
        }

        // ---- 3) pointwise LSTM (register-local gates), write h to smem
#pragma unroll
        for (int mi = 0; mi < 2; mi++)
#pragma unroll
            for (int s = 0; s < 2; s++)
#pragma unroll
                for (int r = 0; r < 4; r++) {
                    float ig = sigm(acc[mi][0][s][r]);
                    float fg = sigm(acc[mi][1][s][r]);
                    float gg = tanhx(acc[mi][2][s][r]);
                    float og = sigm(acc[mi][3][s][r]);
                    float cn = fg * cst[mi][s][r] + ig * gg;
                    cst[mi][s][r] = cn;
                    float h = og * tanhx(cn);
                    int cell = mrow * 32 + mi * 16 + g + (r >> 1) * 8;
                    int hd   = w * 16 + s * 8 + 2 * tq + (r & 1);
                    Hs[cell * HSTR + hd] = h;
                }
        __syncthreads();

        // ---- 4) emit spans whose selected step == st (fp32 GEMV, threads 0..255)
        if (t < 256) {
            const int cc  = t & 63;
            const int wsp = (t >> 6) + 1;
            const int i_cell = i0 + cc;
            const int rem = len - i_cell;
            const int j   = i_cell + wsp - 1;
            if (rem >= 1 && j < LL && min(rem, wsp) == st) {
                float s0 = btri[0], s1 = btri[1];
                const float* hrow = Hs + cc * HSTR;
#pragma unroll 8
                for (int k = 0; k < HD; k++) {
                    float hv = hrow[k];
                    s0 += hv * WtS[k];
                    s1 += hv * WtS[HD + k];
                }
                size_t o = (((size_t)b * LL + i_cell) * LL + j) * 2;
                out[o]     = s0;
                out[o + 1] = s1;
            }
        }
        if (st >= nsteps) break;
    }
}

// ---------------------------------------------------------------------------
extern "C" void kernel_launch(void* const* d_in, const int* in_sizes, int n_in,
                              void* d_out, int out_size) {
    const float* feats = (const float*)d_in[0];
    const float* W_ih  = (const float*)d_in[1];
    const float* W_hh  = (const float*)d_in[2];
    const float* b_ih  = (const float*)d_in[3];
    const float* b_hh  = (const float*)d_in[4];
    const float* W_tri = (const float*)d_in[5];
    const float* b_tri = (const float*)d_in[6];
    const int*   lens  = (const int*)d_in[7];
    float* out = (float*)d_out;

    // 0) zero the 134 MB output via driver memset (near-peak HBM)
    cudaMemsetAsync(d_out, 0, (size_t)out_size * sizeof(float));

    // A) input projection GEMM (tf32 mma) into g_pre
    const int smemA = (BMA + BNA) * ASTR * (int)sizeof(unsigned);   // 55296 B
    cudaFuncSetAttribute((const void*)pre_gemm_kernel,
                         cudaFuncAttributeMaxDynamicSharedMemorySize, smemA);
    dim3 gA(M_TOT / BMA, NG / BNA);
    pre_gemm_kernel<<<gA, 256, smemA>>>(feats, W_ih, b_ih, b_hh, lens);

    // B) fused recurrence (tf32 mma) + emit, 512 threads / 16 warps
    const int smemB = (64 * HSTR + NG * WSTR + NG + 256) * (int)sizeof(float);
    cudaFuncSetAttribute((const void*)lstm_mma_kernel,
                         cudaFuncAttributeMaxDynamicSharedMemorySize, smemB);
    lstm_mma_kernel<<<M_TOT / 64, 512, smemB>>>(W_hh, b_ih, b_hh,
                                                W_tri, b_tri, lens, out);
}

// round 7
// speedup vs baseline: 1.0331x; 1.0331x over previous
#include <cuda_runtime.h>
#include <cuda_bf16.h>

// Problem constants
#define BB   64
#define LL   512
#define HH   256
#define HD   128
#define NG   512            // 4 * HD gates
#define M_TOT (BB*LL)       // 32768 cells / rows

// 64 MB scratch: g_pre[m][n] = feats[m]@W_ih^T + b_ih + b_hh
__device__ float g_pre[(size_t)M_TOT * NG];
// 256 KB: W_hh with k pair-permuted per 8-block (slot = (k&~7)|((k&3)<<1)|((k>>2)&1))
__device__ float W_perm[NG * HD];

__device__ __forceinline__ void mma_tf32(float c[4],
                                         unsigned a0, unsigned a1, unsigned a2, unsigned a3,
                                         unsigned b0, unsigned b1) {
    asm volatile(
        "mma.sync.aligned.m16n8k8.row.col.f32.tf32.tf32.f32 "
        "{%0,%1,%2,%3}, {%4,%5,%6,%7}, {%8,%9}, {%0,%1,%2,%3};"
        : "+f"(c[0]), "+f"(c[1]), "+f"(c[2]), "+f"(c[3])
        : "r"(a0), "r"(a1), "r"(a2), "r"(a3), "r"(b0), "r"(b1));
}

__device__ __forceinline__ void cp_async16(void* smem_dst, const void* gptr) {
    unsigned s = (unsigned)__cvta_generic_to_shared(smem_dst);
    asm volatile("cp.async.cg.shared.global [%0], [%1], 16;" :: "r"(s), "l"(gptr));
}
__device__ __forceinline__ void cp_commit() {
    asm volatile("cp.async.commit_group;");
}
template <int N>
__device__ __forceinline__ void cp_wait() {
    asm volatile("cp.async.wait_group %0;" :: "n"(N));
}

__device__ __forceinline__ float sigm(float x)  { return 1.f / (1.f + __expf(-x)); }
__device__ __forceinline__ float tanhx(float x) { return 2.f / (1.f + __expf(-2.f * x)) - 1.f; }

__device__ __forceinline__ int kslot(int k) {
    return (k & ~7) | ((k & 3) << 1) | ((k >> 2) & 1);
}

// ---------------------------------------------------------------------------
// Kernel P: W_perm[n][kslot(k)] = W_hh[n][k]
// ---------------------------------------------------------------------------
__global__ void perm_kernel(const float* __restrict__ Whh) {
    int i = blockIdx.x * 256 + threadIdx.x;     // 0 .. NG*HD-1
    int n = i >> 7, k = i & 127;
    W_perm[n * HD + kslot(k)] = Whh[i];
}

// ---------------------------------------------------------------------------
// Kernel A: g_pre = tf32_mma(feats @ W_ih^T) + (b_ih + b_hh)
// Block tile 128(M) x 256(N), K chunks of 32, double-buffered cp.async,
// raw fp32 bits fed to HMMA.TF32 (RZ truncation).
// ---------------------------------------------------------------------------
#define BMA 128
#define BNA 256
#define BKA 32
#define ASTR 36

__global__ __launch_bounds__(256, 1) void pre_gemm_kernel(
    const float* __restrict__ A,     // feats  [M_TOT][HH]
    const float* __restrict__ W,     // W_ih   [NG][HH]
    const float* __restrict__ b_ih,
    const float* __restrict__ b_hh,
    const int*   __restrict__ lens)
{
    const int m0 = blockIdx.x * BMA;
    const int n0 = blockIdx.y * BNA;
    const int b  = m0 / LL;
    const int j0 = m0 % LL;
    if (j0 >= lens[b] + 3) return;   // rows never consumed

    extern __shared__ __align__(16) float smA[];
    float* As[2] = { smA,                smA + BMA * ASTR };
    float* Bs[2] = { smA + 2 * BMA * ASTR, smA + 2 * BMA * ASTR + BNA * ASTR };

    const int t    = threadIdx.x;
    const int wid  = t >> 5;
    const int lane = t & 31;
    const int g    = lane >> 2;
    const int tq   = lane & 3;
    const int mw   = (wid & 1) * 64;
    const int nw   = (wid >> 1) * 64;

    float acc[4][8][4];
#pragma unroll
    for (int mi = 0; mi < 4; mi++)
#pragma unroll
        for (int ni = 0; ni < 8; ni++)
#pragma unroll
            for (int r = 0; r < 4; r++) acc[mi][ni][r] = 0.f;

    auto stage = [&](int buf, int kc) {
#pragma unroll
        for (int it = 0; it < 4; it++) {
            int idx = t + 256 * it;          // 0..1023
            int row = idx >> 3;
            int k4  = (idx & 7) * 4;
            cp_async16(As[buf] + row * ASTR + k4,
                       A + (size_t)(m0 + row) * HH + kc + k4);
        }
#pragma unroll
        for (int it = 0; it < 8; it++) {
            int idx = t + 256 * it;          // 0..2047
            int row = idx >> 3;
            int k4  = (idx & 7) * 4;
            cp_async16(Bs[buf] + row * ASTR + k4,
                       W + (size_t)(n0 + row) * HH + kc + k4);
        }
    };

    stage(0, 0);
    cp_commit();

#pragma unroll 1
    for (int c = 0; c < HH / BKA; c++) {
        if (c < HH / BKA - 1) {
            stage((c + 1) & 1, (c + 1) * BKA);
            cp_commit();
            cp_wait<1>();
        } else {
            cp_wait<0>();
        }
        __syncthreads();
        const float* Asb = As[c & 1];
        const float* Bsb = Bs[c & 1];

#pragma unroll
        for (int ks = 0; ks < BKA / 8; ks++) {
            const int kk = ks * 8;
            unsigned a[4][4];
#pragma unroll
            for (int mi = 0; mi < 4; mi++) {
                const unsigned* p = (const unsigned*)(Asb + (mw + mi * 16 + g) * ASTR + kk + tq);
                a[mi][0] = p[0];
                a[mi][1] = p[8 * ASTR];
                a[mi][2] = p[4];
                a[mi][3] = p[8 * ASTR + 4];
            }
#pragma unroll
            for (int ni = 0; ni < 8; ni++) {
                const unsigned* p = (const unsigned*)(Bsb + (nw + ni * 8 + g) * ASTR + kk + tq);
                unsigned b0 = p[0], b1 = p[4];
#pragma unroll
                for (int mi = 0; mi < 4; mi++)
                    mma_tf32(acc[mi][ni], a[mi][0], a[mi][1], a[mi][2], a[mi][3], b0, b1);
            }
        }
        __syncthreads();
    }

#pragma unroll
    for (int ni = 0; ni < 8; ni++) {
        const int n = n0 + nw + ni * 8 + 2 * tq;
        const float bv0 = b_ih[n] + b_hh[n];
        const float bv1 = b_ih[n + 1] + b_hh[n + 1];
#pragma unroll
        for (int mi = 0; mi < 4; mi++) {
            const int m = m0 + mw + mi * 16 + g;
            float2 v01 = make_float2(acc[mi][ni][0] + bv0, acc[mi][ni][1] + bv1);
            float2 v23 = make_float2(acc[mi][ni][2] + bv0, acc[mi][ni][3] + bv1);
            *(float2*)(g_pre + (size_t)m * NG + n)       = v01;
            *(float2*)(g_pre + (size_t)(m + 8) * NG + n) = v23;
        }
    }
}

// ---------------------------------------------------------------------------
// Kernel B: fused 4-step LSTM recurrence (tf32 mma) + emit + scatter.
// 64 cells / 512 threads / 16 warps = 2 M-rows x 8 hd-windows; gate-replicated
// n-windows make pointwise LSTM register-local.  Paired smem layouts: every
// fragment load is one LDS.64; W staged from W_perm via double-buffered
// cp.async. Raw fp32 bits into HMMA.TF32 (no cvt).
// ---------------------------------------------------------------------------
#define KCB   32
#define WSTR2 40    // 40 % 32 == 8 -> conflict-free LDS.64 frags
#define HSTR2 136   // 136 % 32 == 8

__global__ __launch_bounds__(512, 1) void lstm_mma_kernel(
    const float* __restrict__ b_ih,
    const float* __restrict__ b_hh,
    const float* __restrict__ Wtri,  // [2][HD]
    const float* __restrict__ btri,  // [2]
    const int*   __restrict__ lens,
    float*       __restrict__ out)   // [BB][LL][LL][2]
{
    const int blk = blockIdx.x;
    const int b   = blk >> 3;
    const int i0  = (blk & 7) * 64;
    const int len = lens[b];
    if (i0 >= len) return;

    extern __shared__ __align__(16) float sm[];
    float* Ws[2] = { sm, sm + NG * WSTR2 };          // 2 x [512][40]
    float* Hs    = sm + 2 * NG * WSTR2;              // [64][136] paired h
    float* biasS = Hs + 64 * HSTR2;                  // [512]
    float* WtS   = biasS + NG;                       // [256] pair-permuted

    const int t    = threadIdx.x;
    const int wid  = t >> 5;
    const int lane = t & 31;
    const int g    = lane >> 2;
    const int tq   = lane & 3;
    const int w    = wid & 7;                // hd window
    const int mrow = wid >> 3;               // 0/1

    if (t < 256) {
        int row = t >> 7, k = t & 127;
        WtS[row * 128 + kslot(k)] = Wtri[t];
    }
    if (t < NG) biasS[t] = b_ih[t] + b_hh[t];
    __syncthreads();

    float cst[2][2][4];
#pragma unroll
    for (int mi = 0; mi < 2; mi++)
#pragma unroll
        for (int s = 0; s < 2; s++)
#pragma unroll
            for (int r = 0; r < 4; r++) cst[mi][s][r] = 0.f;

    int nsteps = len - i0;
    if (nsteps > 4) nsteps = 4;
    const size_t rowBase = (size_t)b * LL;

    auto stage_w = [&](int buf, int kc) {
#pragma unroll
        for (int it = 0; it < 8; it++) {
            int idx = t + 512 * it;       // 0..4095
            int n   = idx >> 3;           // 0..511
            int c4  = (idx & 7) * 4;      // 0..28
            cp_async16(Ws[buf] + n * WSTR2 + c4, W_perm + n * HD + kc + c4);
        }
    };

#pragma unroll 1
    for (int st = 1; st <= 4; st++) {
        // ---- 1) acc init from g_pre (bias for padded rows)
        float acc[2][4][2][4];   // [mi][gate][s][r]
#pragma unroll
        for (int mi = 0; mi < 2; mi++) {
            const int cell0 = mrow * 32 + mi * 16 + g;
            const int jA = i0 + cell0 + st - 1;       // rows for r0/r1
            const int jB = jA + 8;                    // rows for r2/r3
            const float* srcA = (jA < LL) ? (g_pre + (rowBase + jA) * NG) : biasS;
            const float* srcB = (jB < LL) ? (g_pre + (rowBase + jB) * NG) : biasS;
#pragma unroll
            for (int gi = 0; gi < 4; gi++)
#pragma unroll
                for (int s = 0; s < 2; s++) {
                    const int n = gi * 128 + w * 16 + s * 8 + 2 * tq;
                    float2 vA = *(const float2*)(srcA + n);
                    float2 vB = *(const float2*)(srcB + n);
                    acc[mi][gi][s][0] = vA.x; acc[mi][gi][s][1] = vA.y;
                    acc[mi][gi][s][2] = vB.x; acc[mi][gi][s][3] = vB.y;
                }
        }

        // ---- 2) recurrent tf32 mma: acc += H_prev @ W_hh^T  (h0 = 0 -> skip st 1)
        if (st > 1) {
            stage_w(0, 0);
            cp_commit();
#pragma unroll 1
            for (int ci = 0; ci < HD / KCB; ci++) {
                if (ci < HD / KCB - 1) {
                    stage_w((ci + 1) & 1, (ci + 1) * KCB);
                    cp_commit();
                    cp_wait<1>();
                } else {
                    cp_wait<0>();
                }
                __syncthreads();
                const float* Wsb = Ws[ci & 1];
                const int kc = ci * KCB;
#pragma unroll
                for (int ks = 0; ks < KCB / 8; ks++) {
                    const int kk = ks * 8;
                    unsigned a[2][4];
#pragma unroll
                    for (int mi = 0; mi < 2; mi++) {
                        const int cell = mrow * 32 + mi * 16 + g;
                        uint2 A0 = *((const uint2*)(Hs + cell * HSTR2 + kc + kk) + tq);
                        uint2 A1 = *((const uint2*)(Hs + (cell + 8) * HSTR2 + kc + kk) + tq);
                        a[mi][0] = A0.x; a[mi][1] = A1.x;
                        a[mi][2] = A0.y; a[mi][3] = A1.y;
                    }
#pragma unroll
                    for (int gi = 0; gi < 4; gi++)
#pragma unroll
                        for (int s = 0; s < 2; s++) {
                            const int nrow = gi * 128 + w * 16 + s * 8 + g;
                            uint2 B = *((const uint2*)(Wsb + nrow * WSTR2 + kk) + tq);
#pragma unroll
                            for (int mi = 0; mi < 2; mi++)
                                mma_tf32(acc[mi][gi][s],
                                         a[mi][0], a[mi][1], a[mi][2], a[mi][3], B.x, B.y);
                        }
                }
                __syncthreads();
            }
        }

        // ---- 3) pointwise LSTM (register-local gates), write h to paired Hs
#pragma unroll
        for (int mi = 0; mi < 2; mi++)
#pragma unroll
            for (int s = 0; s < 2; s++)
#pragma unroll
                for (int r = 0; r < 4; r++) {
                    float ig = sigm(acc[mi][0][s][r]);
                    float fg = sigm(acc[mi][1][s][r]);
                    float gg = tanhx(acc[mi][2][s][r]);
                    float og = sigm(acc[mi][3][s][r]);
                    float cn = fg * cst[mi][s][r] + ig * gg;
                    cst[mi][s][r] = cn;
                    float h = og * tanhx(cn);
                    int cell = mrow * 32 + mi * 16 + g + (r >> 1) * 8;
                    int hd   = w * 16 + s * 8 + 2 * tq + (r & 1);
                    Hs[cell * HSTR2 + kslot(hd)] = h;
                }
        __syncthreads();

        // ---- 4) emit spans whose selected step == st (fp32 GEMV, vectorized)
        if (t < 256) {
            const int cc  = t & 63;
            const int wsp = (t >> 6) + 1;
            const int i_cell = i0 + cc;
            const int rem = len - i_cell;
            const int j   = i_cell + wsp - 1;
            if (rem >= 1 && j < LL && min(rem, wsp) == st) {
                float s0 = btri[0], s1 = btri[1];
                const float4* hv4 = (const float4*)(Hs + cc * HSTR2);
                const float4* w04 = (const float4*)(WtS);
                const float4* w14 = (const float4*)(WtS + 128);
#pragma unroll
                for (int q = 0; q < 32; q++) {
                    float4 h = hv4[q], a0 = w04[q], a1 = w14[q];
                    s0 += h.x * a0.x + h.y * a0.y + h.z * a0.z + h.w * a0.w;
                    s1 += h.x * a1.x + h.y * a1.y + h.z * a1.z + h.w * a1.w;
                }
                size_t o = (((size_t)b * LL + i_cell) * LL + j) * 2;
                out[o]     = s0;
                out[o + 1] = s1;
            }
        }
        if (st >= nsteps) break;
    }
}

// ---------------------------------------------------------------------------
extern "C" void kernel_launch(void* const* d_in, const int* in_sizes, int n_in,
                              void* d_out, int out_size) {
    const float* feats = (const float*)d_in[0];
    const float* W_ih  = (const float*)d_in[1];
    const float* W_hh  = (const float*)d_in[2];
    const float* b_ih  = (const float*)d_in[3];
    const float* b_hh  = (const float*)d_in[4];
    const float* W_tri = (const float*)d_in[5];
    const float* b_tri = (const float*)d_in[6];
    const int*   lens  = (const int*)d_in[7];
    float* out = (float*)d_out;

    // 0) zero the 134 MB output via driver memset (near-peak HBM)
    cudaMemsetAsync(d_out, 0, (size_t)out_size * sizeof(float));

    // P) pair-permute W_hh once
    perm_kernel<<<(NG * HD) / 256, 256>>>(W_hh);

    // A) input projection GEMM (tf32 mma, double-buffered) into g_pre
    const int smemA = 2 * (BMA + BNA) * ASTR * (int)sizeof(float);   // 110592 B
    cudaFuncSetAttribute((const void*)pre_gemm_kernel,
                         cudaFuncAttributeMaxDynamicSharedMemorySize, smemA);
    dim3 gA(M_TOT / BMA, NG / BNA);
    pre_gemm_kernel<<<gA, 256, smemA>>>(feats, W_ih, b_ih, b_hh, lens);

    // B) fused recurrence (tf32 mma) + emit, 512 threads / 16 warps
    const int smemB = (2 * NG * WSTR2 + 64 * HSTR2 + NG + 256) * (int)sizeof(float); // 201728 B
    cudaFuncSetAttribute((const void*)lstm_mma_kernel,
                         cudaFuncAttributeMaxDynamicSharedMemorySize, smemB);
    lstm_mma_kernel<<<M_TOT / 64, 512, smemB>>>(b_ih, b_hh,
                                                W_tri, b_tri, lens, out);
}

// round 8
// speedup vs baseline: 1.0340x; 1.0008x over previous
#include <cuda_runtime.h>
#include <cuda_bf16.h>

// Problem constants
#define BB   64
#define LL   512
#define HH   256
#define HD   128
#define NG   512            // 4 * HD gates
#define M_TOT (BB*LL)       // 32768 cells / rows

// 64 MB scratch: g_pre[m][n] = feats[m]@W_ih^T + b_ih + b_hh
__device__ float g_pre[(size_t)M_TOT * NG];
// 256 KB: W_hh with k pair-permuted per 8-block (slot = (k&~7)|((k&3)<<1)|((k>>2)&1))
__device__ float W_perm[NG * HD];

__device__ __forceinline__ void mma_tf32(float c[4],
                                         unsigned a0, unsigned a1, unsigned a2, unsigned a3,
                                         unsigned b0, unsigned b1) {
    asm volatile(
        "mma.sync.aligned.m16n8k8.row.col.f32.tf32.tf32.f32 "
        "{%0,%1,%2,%3}, {%4,%5,%6,%7}, {%8,%9}, {%0,%1,%2,%3};"
        : "+f"(c[0]), "+f"(c[1]), "+f"(c[2]), "+f"(c[3])
        : "r"(a0), "r"(a1), "r"(a2), "r"(a3), "r"(b0), "r"(b1));
}

__device__ __forceinline__ void cp_async16(void* smem_dst, const void* gptr) {
    unsigned s = (unsigned)__cvta_generic_to_shared(smem_dst);
    asm volatile("cp.async.cg.shared.global [%0], [%1], 16;" :: "r"(s), "l"(gptr));
}
__device__ __forceinline__ void cp_commit() {
    asm volatile("cp.async.commit_group;");
}
template <int N>
__device__ __forceinline__ void cp_wait() {
    asm volatile("cp.async.wait_group %0;" :: "n"(N));
}

__device__ __forceinline__ float sigm(float x)  { return 1.f / (1.f + __expf(-x)); }
__device__ __forceinline__ float tanhx(float x) { return 2.f / (1.f + __expf(-2.f * x)) - 1.f; }

__device__ __forceinline__ int kslot(int k) {
    return (k & ~7) | ((k & 3) << 1) | ((k >> 2) & 1);
}

// ---------------------------------------------------------------------------
// Kernel P: W_perm[n][kslot(k)] = W_hh[n][k]
// ---------------------------------------------------------------------------
__global__ void perm_kernel(const float* __restrict__ Whh) {
    int i = blockIdx.x * 256 + threadIdx.x;     // 0 .. NG*HD-1
    int n = i >> 7, k = i & 127;
    W_perm[n * HD + kslot(k)] = Whh[i];
}

// ---------------------------------------------------------------------------
// Kernel A: g_pre = tf32_mma(feats @ W_ih^T) + (b_ih + b_hh)
// Block tile 128(M) x 256(N), K chunks of 32, double-buffered cp.async,
// raw fp32 bits fed to HMMA.TF32 (RZ truncation).
// ---------------------------------------------------------------------------
#define BMA 128
#define BNA 256
#define BKA 32
#define ASTR 36

__global__ __launch_bounds__(256, 1) void pre_gemm_kernel(
    const float* __restrict__ A,     // feats  [M_TOT][HH]
    const float* __restrict__ W,     // W_ih   [NG][HH]
    const float* __restrict__ b_ih,
    const float* __restrict__ b_hh,
    const int*   __restrict__ lens)
{
    const int m0 = blockIdx.x * BMA;
    const int n0 = blockIdx.y * BNA;
    const int b  = m0 / LL;
    const int j0 = m0 % LL;
    if (j0 >= lens[b] + 3) return;   // rows never consumed

    extern __shared__ __align__(16) float smA[];
    float* As[2] = { smA,                smA + BMA * ASTR };
    float* Bs[2] = { smA + 2 * BMA * ASTR, smA + 2 * BMA * ASTR + BNA * ASTR };

    const int t    = threadIdx.x;
    const int wid  = t >> 5;
    const int lane = t & 31;
    const int g    = lane >> 2;
    const int tq   = lane & 3;
    const int mw   = (wid & 1) * 64;
    const int nw   = (wid >> 1) * 64;

    float acc[4][8][4];
#pragma unroll
    for (int mi = 0; mi < 4; mi++)
#pragma unroll
        for (int ni = 0; ni < 8; ni++)
#pragma unroll
            for (int r = 0; r < 4; r++) acc[mi][ni][r] = 0.f;

    auto stage = [&](int buf, int kc) {
#pragma unroll
        for (int it = 0; it < 4; it++) {
            int idx = t + 256 * it;          // 0..1023
            int row = idx >> 3;
            int k4  = (idx & 7) * 4;
            cp_async16(As[buf] + row * ASTR + k4,
                       A + (size_t)(m0 + row) * HH + kc + k4);
        }
#pragma unroll
        for (int it = 0; it < 8; it++) {
            int idx = t + 256 * it;          // 0..2047
            int row = idx >> 3;
            int k4  = (idx & 7) * 4;
            cp_async16(Bs[buf] + row * ASTR + k4,
                       W + (size_t)(n0 + row) * HH + kc + k4);
        }
    };

    stage(0, 0);
    cp_commit();

#pragma unroll 1
    for (int c = 0; c < HH / BKA; c++) {
        if (c < HH / BKA - 1) {
            stage((c + 1) & 1, (c + 1) * BKA);
            cp_commit();
            cp_wait<1>();
        } else {
            cp_wait<0>();
        }
        __syncthreads();
        const float* Asb = As[c & 1];
        const float* Bsb = Bs[c & 1];

#pragma unroll
        for (int ks = 0; ks < BKA / 8; ks++) {
            const int kk = ks * 8;
            unsigned a[4][4];
#pragma unroll
            for (int mi = 0; mi < 4; mi++) {
                const unsigned* p = (const unsigned*)(Asb + (mw + mi * 16 + g) * ASTR + kk + tq);
                a[mi][0] = p[0];
                a[mi][1] = p[8 * ASTR];
                a[mi][2] = p[4];
                a[mi][3] = p[8 * ASTR + 4];
            }
#pragma unroll
            for (int ni = 0; ni < 8; ni++) {
                const unsigned* p = (const unsigned*)(Bsb + (nw + ni * 8 + g) * ASTR + kk + tq);
                unsigned b0 = p[0], b1 = p[4];
#pragma unroll
                for (int mi = 0; mi < 4; mi++)
                    mma_tf32(acc[mi][ni], a[mi][0], a[mi][1], a[mi][2], a[mi][3], b0, b1);
            }
        }
        __syncthreads();
    }

#pragma unroll
    for (int ni = 0; ni < 8; ni++) {
        const int n = n0 + nw + ni * 8 + 2 * tq;
        const float bv0 = b_ih[n] + b_hh[n];
        const float bv1 = b_ih[n + 1] + b_hh[n + 1];
#pragma unroll
        for (int mi = 0; mi < 4; mi++) {
            const int m = m0 + mw + mi * 16 + g;
            float2 v01 = make_float2(acc[mi][ni][0] + bv0, acc[mi][ni][1] + bv1);
            float2 v23 = make_float2(acc[mi][ni][2] + bv0, acc[mi][ni][3] + bv1);
            *(float2*)(g_pre + (size_t)m * NG + n)       = v01;
            *(float2*)(g_pre + (size_t)(m + 8) * NG + n) = v23;
        }
    }
}

// ---------------------------------------------------------------------------
// Kernel B: fused 4-step LSTM recurrence (tf32 mma) + emit + scatter.
// 64 cells / 512 threads / 16 warps = 2 M-rows x 8 hd-windows; gate-replicated
// n-windows make pointwise LSTM register-local.  Paired smem layouts: every
// fragment load is one LDS.64; W staged from W_perm via double-buffered
// cp.async. Raw fp32 bits into HMMA.TF32 (no cvt).
// ---------------------------------------------------------------------------
#define KCB   32
#define WSTR2 40    // 40 % 32 == 8 -> conflict-free LDS.64 frags
#define HSTR2 136   // 136 % 32 == 8

__global__ __launch_bounds__(512, 1) void lstm_mma_kernel(
    const float* __restrict__ b_ih,
    const float* __restrict__ b_hh,
    const float* __restrict__ Wtri,  // [2][HD]
    const float* __restrict__ btri,  // [2]
    const int*   __restrict__ lens,
    float*       __restrict__ out)   // [BB][LL][LL][2]
{
    const int blk = blockIdx.x;
    const int b   = blk >> 3;
    const int i0  = (blk & 7) * 64;
    const int len = lens[b];
    if (i0 >= len) return;

    extern __shared__ __align__(16) float sm[];
    float* Ws[2] = { sm, sm + NG * WSTR2 };          // 2 x [512][40]
    float* Hs    = sm + 2 * NG * WSTR2;              // [64][136] paired h
    float* biasS = Hs + 64 * HSTR2;                  // [512]
    float* WtS   = biasS + NG;                       // [256] pair-permuted

    const int t    = threadIdx.x;
    const int wid  = t >> 5;
    const int lane = t & 31;
    const int g    = lane >> 2;
    const int tq   = lane & 3;
    const int w    = wid & 7;                // hd window
    const int mrow = wid >> 3;               // 0/1

    if (t < 256) {
        int row = t >> 7, k = t & 127;
        WtS[row * 128 + kslot(k)] = Wtri[t];
    }
    if (t < NG) biasS[t] = b_ih[t] + b_hh[t];
    __syncthreads();

    float cst[2][2][4];
#pragma unroll
    for (int mi = 0; mi < 2; mi++)
#pragma unroll
        for (int s = 0; s < 2; s++)
#pragma unroll
            for (int r = 0; r < 4; r++) cst[mi][s][r] = 0.f;

    int nsteps = len - i0;
    if (nsteps > 4) nsteps = 4;
    const size_t rowBase = (size_t)b * LL;

    auto stage_w = [&](int buf, int kc) {
#pragma unroll
        for (int it = 0; it < 8; it++) {
            int idx = t + 512 * it;       // 0..4095
            int n   = idx >> 3;           // 0..511
            int c4  = (idx & 7) * 4;      // 0..28
            cp_async16(Ws[buf] + n * WSTR2 + c4, W_perm + n * HD + kc + c4);
        }
    };

#pragma unroll 1
    for (int st = 1; st <= 4; st++) {
        // ---- 1) acc init from g_pre (bias for padded rows)
        float acc[2][4][2][4];   // [mi][gate][s][r]
#pragma unroll
        for (int mi = 0; mi < 2; mi++) {
            const int cell0 = mrow * 32 + mi * 16 + g;
            const int jA = i0 + cell0 + st - 1;       // rows for r0/r1
            const int jB = jA + 8;                    // rows for r2/r3
            const float* srcA = (jA < LL) ? (g_pre + (rowBase + jA) * NG) : biasS;
            const float* srcB = (jB < LL) ? (g_pre + (rowBase + jB) * NG) : biasS;
#pragma unroll
            for (int gi = 0; gi < 4; gi++)
#pragma unroll
                for (int s = 0; s < 2; s++) {
                    const int n = gi * 128 + w * 16 + s * 8 + 2 * tq;
                    float2 vA = *(const float2*)(srcA + n);
                    float2 vB = *(const float2*)(srcB + n);
                    acc[mi][gi][s][0] = vA.x; acc[mi][gi][s][1] = vA.y;
                    acc[mi][gi][s][2] = vB.x; acc[mi][gi][s][3] = vB.y;
                }
        }

        // ---- 2) recurrent tf32 mma: acc += H_prev @ W_hh^T  (h0 = 0 -> skip st 1)
        if (st > 1) {
            stage_w(0, 0);
            cp_commit();
#pragma unroll 1
            for (int ci = 0; ci < HD / KCB; ci++) {
                if (ci < HD / KCB - 1) {
                    stage_w((ci + 1) & 1, (ci + 1) * KCB);
                    cp_commit();
                    cp_wait<1>();
                } else {
                    cp_wait<0>();
                }
                __syncthreads();
                const float* Wsb = Ws[ci & 1];
                const int kc = ci * KCB;
#pragma unroll
                for (int ks = 0; ks < KCB / 8; ks++) {
                    const int kk = ks * 8;
                    unsigned a[2][4];
#pragma unroll
                    for (int mi = 0; mi < 2; mi++) {
                        const int cell = mrow * 32 + mi * 16 + g;
                        uint2 A0 = *((const uint2*)(Hs + cell * HSTR2 + kc + kk) + tq);
                        uint2 A1 = *((const uint2*)(Hs + (cell + 8) * HSTR2 + kc + kk) + tq);
                        a[mi][0] = A0.x; a[mi][1] = A1.x;
                        a[mi][2] = A0.y; a[mi][3] = A1.y;
                    }
#pragma unroll
                    for (int gi = 0; gi < 4; gi++)
#pragma unroll
                        for (int s = 0; s < 2; s++) {
                            const int nrow = gi * 128 + w * 16 + s * 8 + g;
                            uint2 B = *((const uint2*)(Wsb + nrow * WSTR2 + kk) + tq);
#pragma unroll
                            for (int mi = 0; mi < 2; mi++)
                                mma_tf32(acc[mi][gi][s],
                                         a[mi][0], a[mi][1], a[mi][2], a[mi][3], B.x, B.y);
                        }
                }
                __syncthreads();
            }
        }

        // ---- 3) pointwise LSTM (register-local gates), write h to paired Hs
#pragma unroll
        for (int mi = 0; mi < 2; mi++)
#pragma unroll
            for (int s = 0; s < 2; s++)
#pragma unroll
                for (int r = 0; r < 4; r++) {
                    float ig = sigm(acc[mi][0][s][r]);
                    float fg = sigm(acc[mi][1][s][r]);
                    float gg = tanhx(acc[mi][2][s][r]);
                    float og = sigm(acc[mi][3][s][r]);
                    float cn = fg * cst[mi][s][r] + ig * gg;
                    cst[mi][s][r] = cn;
                    float h = og * tanhx(cn);
                    int cell = mrow * 32 + mi * 16 + g + (r >> 1) * 8;
                    int hd   = w * 16 + s * 8 + 2 * tq + (r & 1);
                    Hs[cell * HSTR2 + kslot(hd)] = h;
                }
        __syncthreads();

        // ---- 4) emit spans whose selected step == st (fp32 GEMV, vectorized)
        if (t < 256) {
            const int cc  = t & 63;
            const int wsp = (t >> 6) + 1;
            const int i_cell = i0 + cc;
            const int rem = len - i_cell;
            const int j   = i_cell + wsp - 1;
            if (rem >= 1 && j < LL && min(rem, wsp) == st) {
                float s0 = btri[0], s1 = btri[1];
                const float4* hv4 = (const float4*)(Hs + cc * HSTR2);
                const float4* w04 = (const float4*)(WtS);
                const float4* w14 = (const float4*)(WtS + 128);
#pragma unroll
                for (int q = 0; q < 32; q++) {
                    float4 h = hv4[q], a0 = w04[q], a1 = w14[q];
                    s0 += h.x * a0.x + h.y * a0.y + h.z * a0.z + h.w * a0.w;
                    s1 += h.x * a1.x + h.y * a1.y + h.z * a1.z + h.w * a1.w;
                }
                size_t o = (((size_t)b * LL + i_cell) * LL + j) * 2;
                out[o]     = s0;
                out[o + 1] = s1;
            }
        }
        if (st >= nsteps) break;
    }
}

// ---------------------------------------------------------------------------
extern "C" void kernel_launch(void* const* d_in, const int* in_sizes, int n_in,
                              void* d_out, int out_size) {
    const float* feats = (const float*)d_in[0];
    const float* W_ih  = (const float*)d_in[1];
    const float* W_hh  = (const float*)d_in[2];
    const float* b_ih  = (const float*)d_in[3];
    const float* b_hh  = (const float*)d_in[4];
    const float* W_tri = (const float*)d_in[5];
    const float* b_tri = (const float*)d_in[6];
    const int*   lens  = (const int*)d_in[7];
    float* out = (float*)d_out;

    // 0) zero the 134 MB output via driver memset (near-peak HBM)
    cudaMemsetAsync(d_out, 0, (size_t)out_size * sizeof(float));

    // P) pair-permute W_hh once
    perm_kernel<<<(NG * HD) / 256, 256>>>(W_hh);

    // A) input projection GEMM (tf32 mma, double-buffered) into g_pre
    const int smemA = 2 * (BMA + BNA) * ASTR * (int)sizeof(float);   // 110592 B
    cudaFuncSetAttribute((const void*)pre_gemm_kernel,
                         cudaFuncAttributeMaxDynamicSharedMemorySize, smemA);
    dim3 gA(M_TOT / BMA, NG / BNA);
    pre_gemm_kernel<<<gA, 256, smemA>>>(feats, W_ih, b_ih, b_hh, lens);

    // B) fused recurrence (tf32 mma) + emit, 512 threads / 16 warps
    const int smemB = (2 * NG * WSTR2 + 64 * HSTR2 + NG + 256) * (int)sizeof(float); // 201728 B
    cudaFuncSetAttribute((const void*)lstm_mma_kernel,
                         cudaFuncAttributeMaxDynamicSharedMemorySize, smemB);
    lstm_mma_kernel<<<M_TOT / 64, 512, smemB>>>(b_ih, b_hh,
                                                W_tri, b_tri, lens, out);
}